// round 13
// baseline (speedup 1.0000x reference)
// R12 resubmit (R12 run hit container-infra failure; kernel never executed).
#include <cuda_runtime.h>
#include <cuda_fp16.h>
#include <cstdint>

// Problem dims (fixed)
#define T_DIM 256
#define H_DIM 4096
#define I_DIM 14336
#define GS 64
#define NG1 (H_DIM / GS)   // 64
#define NG2 (I_DIM / GS)   // 224
#define KSPLIT 7
#define NC2_SPLIT (NG2 / KSPLIT)   // 32 chunks per split

#define SSTR 72            // smem row stride in halves (64 + 8 pad)

// Scratch (static __device__: allocation-free per harness rules)
__device__ __half g_xh[T_DIM * H_DIM];              // x in fp16
__device__ __half g_gate[T_DIM * I_DIM];            // raw gate fp16
__device__ __half g_up[T_DIM * I_DIM];              // raw up fp16
__device__ __half g_hh[T_DIM * I_DIM];              // silu(gate)*up fp16
__device__ float  g_part[KSPLIT][T_DIM * H_DIM];    // down-GEMM split-K partials

__device__ __forceinline__ uint32_t h2_as_u32(__half2 h) {
    union { __half2 h2; uint32_t u; } cvt; cvt.h2 = h; return cvt.u;
}
__device__ __forceinline__ unsigned smem_u32(const void* p) {
    return (unsigned)__cvta_generic_to_shared(p);
}
__device__ __forceinline__ void cp_async16(void* dst, const void* src) {
    asm volatile("cp.async.cg.shared.global [%0], [%1], 16;\n"
                 :: "r"(smem_u32(dst)), "l"(src));
}
__device__ __forceinline__ void cp_commit() { asm volatile("cp.async.commit_group;\n"); }
template<int N> __device__ __forceinline__ void cp_wait() {
    asm volatile("cp.async.wait_group %0;\n" :: "n"(N));
    __syncwarp();
}
__device__ __forceinline__ void mma16816(float* c, const uint32_t* a, uint32_t b0, uint32_t b1) {
    asm volatile(
        "mma.sync.aligned.m16n8k16.row.col.f32.f16.f16.f32 "
        "{%0,%1,%2,%3}, {%4,%5,%6,%7}, {%8,%9}, {%0,%1,%2,%3};\n"
        : "+f"(c[0]), "+f"(c[1]), "+f"(c[2]), "+f"(c[3])
        : "r"(a[0]), "r"(a[1]), "r"(a[2]), "r"(a[3]), "r"(b0), "r"(b1));
}
__device__ __forceinline__ void ldsm4(uint32_t* r, uint32_t addr) {
    asm volatile("ldmatrix.sync.aligned.m8n8.x4.shared.b16 {%0,%1,%2,%3}, [%4];"
                 : "=r"(r[0]), "=r"(r[1]), "=r"(r[2]), "=r"(r[3]) : "r"(addr));
}

// ---------------------------------------------------------------------------
// Kernel 0: x fp32 -> fp16
// ---------------------------------------------------------------------------
__global__ void cvt_x_kernel(const float* __restrict__ x) {
    int i = (blockIdx.x * blockDim.x + threadIdx.x) * 4;
    float4 v = *(const float4*)(x + i);
    *(__half2*)&g_xh[i]     = __floats2half2_rn(v.x, v.y);
    *(__half2*)&g_xh[i + 2] = __floats2half2_rn(v.z, v.w);
}

// ---------------------------------------------------------------------------
// Shared GEMM core: BM=128, BN=128, BK=64, 512 threads (16 warps, 4x4),
// warp tile 32x32 (acc 32 regs). Two barriers per chunk (race-free, R7-style).
// A cp.async double-buffered; B int32 HQQ register-staged one chunk ahead,
// dequant -> fp16 smem at consume time. Fragments via ldmatrix.x4.
// 1 CTA/SM = 16 warps/SM (same concurrency as 2x256, -23% smem bytes/MAC).
// ---------------------------------------------------------------------------
struct GemmCore {
    const __half* gA; int lda;
    const int* wq_row; const float* ws_row; const float* wz_row;
    int t0;
    int nchunks; int kc0;   // chunk range [kc0, kc0+nchunks)
};

__device__ __forceinline__ void gemm_core_run(const GemmCore& g, char* smem, float acc[2][4][4]) {
    __half* As = (__half*)smem;                          // [2][128][SSTR]
    __half* Bs = (__half*)(smem + 2 * 128 * SSTR * 2);   // [2][128][SSTR]

    const int tid  = threadIdx.x;
    const int lane = tid & 31;
    const int wid  = tid >> 5;   // 0..15
    const int wm   = wid & 3;    // 4 warp rows
    const int wn   = wid >> 2;   // 4 warp cols

    const int br = tid >> 2;          // 0..127 (B row)
    const int bk = (tid & 3) * 16;

    int4 q[4]; float s, z;

    // prologue: A chunk 0 (2 x cp.async16/thread), B chunk 0 staged
#pragma unroll
    for (int j = 0; j < 2; j++) {
        int v = tid + j * 512, r = v >> 3, c = (v & 7) * 8;
        cp_async16(As + r * SSTR + c, g.gA + (size_t)(g.t0 + r) * g.lda + g.kc0 * 64 + c);
    }
    cp_commit();
#pragma unroll
    for (int j = 0; j < 4; j++) q[j] = *(const int4*)(g.wq_row + (size_t)g.kc0 * 64 + j * 4);
    s = g.ws_row[g.kc0]; z = g.wz_row[g.kc0];

    // ldmatrix per-lane addresses (bytes)
    const int lrow = lane & 15, lcol = lane >> 4;
    const uint32_t As_u = smem_u32(As);
    const uint32_t Bs_u = smem_u32(Bs);
    uint32_t a_addr[2], b_addr[2];
#pragma unroll
    for (int mi = 0; mi < 2; mi++)
        a_addr[mi] = As_u + ((wm * 32 + mi * 16 + lrow) * SSTR + lcol * 8) * 2;
#pragma unroll
    for (int nj = 0; nj < 2; nj++)
        b_addr[nj] = Bs_u + ((wn * 32 + nj * 16 + lrow) * SSTR + lcol * 8) * 2;

    const int NC = g.nchunks;
    for (int kl = 0; kl < NC; kl++) {
        const int buf = kl & 1;
        if (kl + 1 < NC) {
#pragma unroll
            for (int j = 0; j < 2; j++) {
                int v = tid + j * 512, r = v >> 3, c = (v & 7) * 8;
                cp_async16(As + (buf ^ 1) * 128 * SSTR + r * SSTR + c,
                           g.gA + (size_t)(g.t0 + r) * g.lda + (g.kc0 + kl + 1) * 64 + c);
            }
            cp_commit();
            cp_wait<1>();      // own-thread A[kl] landed
        } else {
            cp_wait<0>();
        }

        // dequant staged B[kl] -> fp16 smem
        {
            __half* bp = Bs + buf * 128 * SSTR + br * SSTR + bk;
#pragma unroll
            for (int jj = 0; jj < 2; jj++) {
                uint4 v;
                int4 qa = q[jj * 2], qb = q[jj * 2 + 1];
                v.x = h2_as_u32(__floats2half2_rn(((float)qa.x - z) * s, ((float)qa.y - z) * s));
                v.y = h2_as_u32(__floats2half2_rn(((float)qa.z - z) * s, ((float)qa.w - z) * s));
                v.z = h2_as_u32(__floats2half2_rn(((float)qb.x - z) * s, ((float)qb.y - z) * s));
                v.w = h2_as_u32(__floats2half2_rn(((float)qb.z - z) * s, ((float)qb.w - z) * s));
                *(uint4*)(bp + jj * 8) = v;
            }
        }
        __syncthreads();   // barrier 1: all STS done AND all threads' A-waits passed

        if (kl + 1 < NC) {   // stage B[kl+1] (LDG hidden under MMA)
#pragma unroll
            for (int j = 0; j < 4; j++)
                q[j] = *(const int4*)(g.wq_row + (size_t)(g.kc0 + kl + 1) * 64 + j * 4);
            s = g.ws_row[g.kc0 + kl + 1]; z = g.wz_row[g.kc0 + kl + 1];
        }

        const uint32_t abuf = buf * 128 * SSTR * 2;
        const uint32_t bbuf = buf * 128 * SSTR * 2;
#pragma unroll
        for (int ks = 0; ks < 4; ks++) {
            const uint32_t ko = ks * 32;   // 16 halves per k-step
            uint32_t af[2][4], bf[2][4];
            ldsm4(af[0], a_addr[0] + abuf + ko);
            ldsm4(af[1], a_addr[1] + abuf + ko);
            ldsm4(bf[0], b_addr[0] + bbuf + ko);
            ldsm4(bf[1], b_addr[1] + bbuf + ko);
#pragma unroll
            for (int mi = 0; mi < 2; mi++) {
                mma16816(acc[mi][0], af[mi], bf[0][0], bf[0][2]);
                mma16816(acc[mi][1], af[mi], bf[0][1], bf[0][3]);
                mma16816(acc[mi][2], af[mi], bf[1][0], bf[1][2]);
                mma16816(acc[mi][3], af[mi], bf[1][1], bf[1][3]);
            }
        }
        __syncthreads();   // barrier 2: MMA reads done before buffers overwritten
    }
}

// ---------------------------------------------------------------------------
// Projection GEMM (gate & up): z=0 -> w1 -> g_gate, z=1 -> w3 -> g_up (fp16).
// grid (T/128, I/128, 2) = 448 CTAs, 512 threads
// ---------------------------------------------------------------------------
__global__ void __launch_bounds__(512, 1) gemm_proj(
    const int* __restrict__ w1q, const float* __restrict__ w1s, const float* __restrict__ w1z,
    const int* __restrict__ w3q, const float* __restrict__ w3s, const float* __restrict__ w3z)
{
    extern __shared__ char smem[];
    const int t0 = blockIdx.x * 128;
    const int i0 = blockIdx.y * 128;
    const bool up = blockIdx.z != 0;

    const int*   wq = up ? w3q : w1q;
    const float* ws = up ? w3s : w1s;
    const float* wz = up ? w3z : w1z;
    __half* outp = up ? g_up : g_gate;

    const int tid = threadIdx.x;
    const int br  = tid >> 2;

    GemmCore g;
    g.gA = g_xh; g.lda = H_DIM;
    g.wq_row = wq + (size_t)(i0 + br) * H_DIM + (tid & 3) * 16;
    g.ws_row = ws + (size_t)(i0 + br) * NG1;
    g.wz_row = wz + (size_t)(i0 + br) * NG1;
    g.t0 = t0; g.nchunks = NG1; g.kc0 = 0;

    float acc[2][4][4];
#pragma unroll
    for (int mi = 0; mi < 2; mi++)
#pragma unroll
        for (int ni = 0; ni < 4; ni++)
#pragma unroll
            for (int r = 0; r < 4; r++) acc[mi][ni][r] = 0.f;

    gemm_core_run(g, smem, acc);

    const int lane = tid & 31, wid = tid >> 5, wm = wid & 3, wn = wid >> 2;
#pragma unroll
    for (int mi = 0; mi < 2; mi++) {
#pragma unroll
        for (int ni = 0; ni < 4; ni++) {
            int r0  = t0 + wm * 32 + mi * 16 + (lane >> 2);
            int col = i0 + wn * 32 + ni * 8 + (lane & 3) * 2;
            *(__half2*)&outp[(size_t)r0 * I_DIM + col] =
                __floats2half2_rn(acc[mi][ni][0], acc[mi][ni][1]);
            *(__half2*)&outp[(size_t)(r0 + 8) * I_DIM + col] =
                __floats2half2_rn(acc[mi][ni][2], acc[mi][ni][3]);
        }
    }
}

// ---------------------------------------------------------------------------
// Activation: g_hh = silu(g_gate) * g_up  (fp16 in/out; 8 elems/thread)
// ---------------------------------------------------------------------------
__global__ void act_kernel() {
    int i = (blockIdx.x * blockDim.x + threadIdx.x) * 8;
    uint4 gv = *(const uint4*)&g_gate[i];
    uint4 uv = *(const uint4*)&g_up[i];
    const uint32_t* gp = (const uint32_t*)&gv;
    const uint32_t* upp = (const uint32_t*)&uv;
    uint4 hv;
    uint32_t* hp = (uint32_t*)&hv;
#pragma unroll
    for (int j = 0; j < 4; j++) {
        __half2 gh = *(const __half2*)&gp[j];
        __half2 uh = *(const __half2*)&upp[j];
        float g0 = __low2float(gh), g1 = __high2float(gh);
        float u0 = __low2float(uh), u1 = __high2float(uh);
        float h0 = g0 / (1.f + __expf(-g0)) * u0;
        float h1 = g1 / (1.f + __expf(-g1)) * u1;
        hp[j] = h2_as_u32(__floats2half2_rn(h0, h1));
    }
    *(uint4*)&g_hh[i] = hv;
}

// ---------------------------------------------------------------------------
// Down GEMM, split-K=7: partials into g_part[z]. grid (T/128, H/128, 7) = 448
// ---------------------------------------------------------------------------
__global__ void __launch_bounds__(512, 1) gemm_down(
    const int* __restrict__ wq, const float* __restrict__ ws, const float* __restrict__ wz)
{
    extern __shared__ char smem[];
    const int t0  = blockIdx.x * 128;
    const int h0  = blockIdx.y * 128;
    const int spl = blockIdx.z;

    const int tid = threadIdx.x;
    const int br  = tid >> 2;

    GemmCore g;
    g.gA = g_hh; g.lda = I_DIM;
    g.wq_row = wq + (size_t)(h0 + br) * I_DIM + (tid & 3) * 16;
    g.ws_row = ws + (size_t)(h0 + br) * NG2;
    g.wz_row = wz + (size_t)(h0 + br) * NG2;
    g.t0 = t0; g.nchunks = NC2_SPLIT; g.kc0 = spl * NC2_SPLIT;

    float acc[2][4][4];
#pragma unroll
    for (int mi = 0; mi < 2; mi++)
#pragma unroll
        for (int ni = 0; ni < 4; ni++)
#pragma unroll
            for (int r = 0; r < 4; r++) acc[mi][ni][r] = 0.f;

    gemm_core_run(g, smem, acc);

    const int lane = tid & 31, wid = tid >> 5, wm = wid & 3, wn = wid >> 2;
    float* outp = g_part[spl];
#pragma unroll
    for (int mi = 0; mi < 2; mi++) {
#pragma unroll
        for (int ni = 0; ni < 4; ni++) {
            int r0  = t0 + wm * 32 + mi * 16 + (lane >> 2);
            int col = h0 + wn * 32 + ni * 8 + (lane & 3) * 2;
            *(float2*)&outp[(size_t)r0 * H_DIM + col] =
                make_float2(acc[mi][ni][0], acc[mi][ni][1]);
            *(float2*)&outp[(size_t)(r0 + 8) * H_DIM + col] =
                make_float2(acc[mi][ni][2], acc[mi][ni][3]);
        }
    }
}

// ---------------------------------------------------------------------------
// Reduce split-K partials -> out
// ---------------------------------------------------------------------------
__global__ void reduce_kernel(float* __restrict__ out) {
    int i = (blockIdx.x * blockDim.x + threadIdx.x) * 4;
    float4 r = *(const float4*)&g_part[0][i];
#pragma unroll
    for (int p = 1; p < KSPLIT; p++) {
        float4 v = *(const float4*)&g_part[p][i];
        r.x += v.x; r.y += v.y; r.z += v.z; r.w += v.w;
    }
    *(float4*)&out[i] = r;
}

// ---------------------------------------------------------------------------
#define SMEM_GEMM (4 * 128 * SSTR * 2)   // 73.7 KB (A 2x + B 2x, 128 rows each)

extern "C" void kernel_launch(void* const* d_in, const int* in_sizes, int n_in,
                              void* d_out, int out_size) {
    (void)in_sizes; (void)n_in; (void)out_size;
    const float* x   = (const float*)d_in[0];
    const int*   w1q = (const int*)  d_in[1];
    const float* w1s = (const float*)d_in[2];
    const float* w1z = (const float*)d_in[3];
    const int*   w3q = (const int*)  d_in[4];
    const float* w3s = (const float*)d_in[5];
    const float* w3z = (const float*)d_in[6];
    const int*   w2q = (const int*)  d_in[7];
    const float* w2s = (const float*)d_in[8];
    const float* w2z = (const float*)d_in[9];
    float* out = (float*)d_out;

    cudaFuncSetAttribute(gemm_proj, cudaFuncAttributeMaxDynamicSharedMemorySize, SMEM_GEMM);
    cudaFuncSetAttribute(gemm_down, cudaFuncAttributeMaxDynamicSharedMemorySize, SMEM_GEMM);

    cvt_x_kernel<<<(T_DIM * H_DIM) / 1024, 256>>>(x);
    gemm_proj<<<dim3(T_DIM / 128, I_DIM / 128, 2), 512, SMEM_GEMM>>>(w1q, w1s, w1z, w3q, w3s, w3z);
    act_kernel<<<(T_DIM * I_DIM) / 2048, 256>>>();
    gemm_down<<<dim3(T_DIM / 128, H_DIM / 128, KSPLIT), 512, SMEM_GEMM>>>(w2q, w2s, w2z);
    reduce_kernel<<<(T_DIM * H_DIM) / 1024, 256>>>(out);
}

// round 14
// speedup vs baseline: 1.1919x; 1.1919x over previous
#include <cuda_runtime.h>
#include <cuda_fp16.h>
#include <cstdint>

// Problem dims (fixed)
#define T_DIM 256
#define H_DIM 4096
#define I_DIM 14336
#define GS 64
#define NG1 (H_DIM / GS)   // 64
#define NG2 (I_DIM / GS)   // 224
#define KSPLIT 4
#define NC2_SPLIT (NG2 / KSPLIT)   // 56 chunks per split

#define SSTR 72            // smem row stride in halves (64 + 8 pad)

// Scratch (static __device__: allocation-free per harness rules)
__device__ __half g_xh[T_DIM * H_DIM];              // x in fp16
__device__ __half g_gate[T_DIM * I_DIM];            // raw gate fp16
__device__ __half g_up[T_DIM * I_DIM];              // raw up fp16
__device__ __half g_hh[T_DIM * I_DIM];              // silu(gate)*up fp16
__device__ float  g_part[KSPLIT][T_DIM * H_DIM];    // down-GEMM split-K partials

__device__ __forceinline__ uint32_t h2_as_u32(__half2 h) {
    union { __half2 h2; uint32_t u; } cvt; cvt.h2 = h; return cvt.u;
}
__device__ __forceinline__ unsigned smem_u32(const void* p) {
    return (unsigned)__cvta_generic_to_shared(p);
}
__device__ __forceinline__ void cp_async16(void* dst, const void* src) {
    asm volatile("cp.async.cg.shared.global [%0], [%1], 16;\n"
                 :: "r"(smem_u32(dst)), "l"(src));
}
__device__ __forceinline__ void cp_commit() { asm volatile("cp.async.commit_group;\n"); }
template<int N> __device__ __forceinline__ void cp_wait() {
    asm volatile("cp.async.wait_group %0;\n" :: "n"(N));
    __syncwarp();
}
__device__ __forceinline__ void mma16816(float* c, const uint32_t* a, uint32_t b0, uint32_t b1) {
    asm volatile(
        "mma.sync.aligned.m16n8k16.row.col.f32.f16.f16.f32 "
        "{%0,%1,%2,%3}, {%4,%5,%6,%7}, {%8,%9}, {%0,%1,%2,%3};\n"
        : "+f"(c[0]), "+f"(c[1]), "+f"(c[2]), "+f"(c[3])
        : "r"(a[0]), "r"(a[1]), "r"(a[2]), "r"(a[3]), "r"(b0), "r"(b1));
}
__device__ __forceinline__ void ldsm4(uint32_t* r, uint32_t addr) {
    asm volatile("ldmatrix.sync.aligned.m8n8.x4.shared.b16 {%0,%1,%2,%3}, [%4];"
                 : "=r"(r[0]), "=r"(r[1]), "=r"(r[2]), "=r"(r[3]) : "r"(addr));
}

// ---------------------------------------------------------------------------
// Kernel 0: x fp32 -> fp16
// ---------------------------------------------------------------------------
__global__ void cvt_x_kernel(const float* __restrict__ x) {
    int i = (blockIdx.x * blockDim.x + threadIdx.x) * 4;
    float4 v = *(const float4*)(x + i);
    *(__half2*)&g_xh[i]     = __floats2half2_rn(v.x, v.y);
    *(__half2*)&g_xh[i + 2] = __floats2half2_rn(v.z, v.w);
}

// ---------------------------------------------------------------------------
// Shared GEMM core (R7 structure — proven fastest & race-free):
// BM=128, BN=64, BK=64, 256 threads (8 warps, 4x2), warp tile 32x32.
// A cp.async double-buffered; B int32 HQQ register-staged one chunk ahead,
// dequant -> fp16 smem at consume time. Fragments via ldmatrix.x4.
// Two barriers per chunk; 2 CTAs/SM.
// ---------------------------------------------------------------------------
struct GemmCore {
    const __half* gA; int lda;
    const int* wq_row; const float* ws_row; const float* wz_row;
    int t0;
    int nchunks; int kc0;   // chunk range [kc0, kc0+nchunks)
};

__device__ __forceinline__ void gemm_core_run(const GemmCore& g, char* smem, float acc[2][4][4]) {
    __half* As = (__half*)smem;                          // [2][128][SSTR]
    __half* Bs = (__half*)(smem + 2 * 128 * SSTR * 2);   // [2][64][SSTR]

    const int tid  = threadIdx.x;
    const int lane = tid & 31;
    const int wid  = tid >> 5;
    const int wm   = wid & 3;
    const int wn   = wid >> 2;

    const int br = tid >> 2;          // 0..63
    const int bk = (tid & 3) * 16;

    int4 q[4]; float s, z;

    // prologue: A chunk 0, B chunk 0
#pragma unroll
    for (int j = 0; j < 4; j++) {
        int v = tid + j * 256, r = v >> 3, c = (v & 7) * 8;
        cp_async16(As + r * SSTR + c, g.gA + (size_t)(g.t0 + r) * g.lda + g.kc0 * 64 + c);
    }
    cp_commit();
#pragma unroll
    for (int j = 0; j < 4; j++) q[j] = *(const int4*)(g.wq_row + (size_t)g.kc0 * 64 + j * 4);
    s = g.ws_row[g.kc0]; z = g.wz_row[g.kc0];

    // ldmatrix per-lane addresses (bytes)
    const int lrow = lane & 15, lcol = lane >> 4;
    const uint32_t As_u = smem_u32(As);
    const uint32_t Bs_u = smem_u32(Bs);
    uint32_t a_addr[2], b_addr[2];
#pragma unroll
    for (int mi = 0; mi < 2; mi++)
        a_addr[mi] = As_u + ((wm * 32 + mi * 16 + lrow) * SSTR + lcol * 8) * 2;
#pragma unroll
    for (int nj = 0; nj < 2; nj++)
        b_addr[nj] = Bs_u + ((wn * 32 + nj * 16 + lrow) * SSTR + lcol * 8) * 2;

    const int NC = g.nchunks;
    for (int kl = 0; kl < NC; kl++) {
        const int buf = kl & 1;
        if (kl + 1 < NC) {
#pragma unroll
            for (int j = 0; j < 4; j++) {
                int v = tid + j * 256, r = v >> 3, c = (v & 7) * 8;
                cp_async16(As + (buf ^ 1) * 128 * SSTR + r * SSTR + c,
                           g.gA + (size_t)(g.t0 + r) * g.lda + (g.kc0 + kl + 1) * 64 + c);
            }
            cp_commit();
            cp_wait<1>();      // own-thread A[kl] landed
        } else {
            cp_wait<0>();
        }

        // dequant staged B[kl] -> fp16 smem
        {
            __half* bp = Bs + buf * 64 * SSTR + br * SSTR + bk;
#pragma unroll
            for (int jj = 0; jj < 2; jj++) {
                uint4 v;
                int4 qa = q[jj * 2], qb = q[jj * 2 + 1];
                v.x = h2_as_u32(__floats2half2_rn(((float)qa.x - z) * s, ((float)qa.y - z) * s));
                v.y = h2_as_u32(__floats2half2_rn(((float)qa.z - z) * s, ((float)qa.w - z) * s));
                v.z = h2_as_u32(__floats2half2_rn(((float)qb.x - z) * s, ((float)qb.y - z) * s));
                v.w = h2_as_u32(__floats2half2_rn(((float)qb.z - z) * s, ((float)qb.w - z) * s));
                *(uint4*)(bp + jj * 8) = v;
            }
        }
        __syncthreads();   // barrier 1: STS done AND all threads' A-waits passed

        if (kl + 1 < NC) {   // stage B[kl+1] (LDG hidden under MMA)
#pragma unroll
            for (int j = 0; j < 4; j++)
                q[j] = *(const int4*)(g.wq_row + (size_t)(g.kc0 + kl + 1) * 64 + j * 4);
            s = g.ws_row[g.kc0 + kl + 1]; z = g.wz_row[g.kc0 + kl + 1];
        }

        const uint32_t abuf = buf * 128 * SSTR * 2;
        const uint32_t bbuf = buf * 64 * SSTR * 2;
#pragma unroll
        for (int ks = 0; ks < 4; ks++) {
            const uint32_t ko = ks * 32;   // 16 halves per k-step
            uint32_t af[2][4], bf[2][4];
            ldsm4(af[0], a_addr[0] + abuf + ko);
            ldsm4(af[1], a_addr[1] + abuf + ko);
            ldsm4(bf[0], b_addr[0] + bbuf + ko);
            ldsm4(bf[1], b_addr[1] + bbuf + ko);
#pragma unroll
            for (int mi = 0; mi < 2; mi++) {
                mma16816(acc[mi][0], af[mi], bf[0][0], bf[0][2]);
                mma16816(acc[mi][1], af[mi], bf[0][1], bf[0][3]);
                mma16816(acc[mi][2], af[mi], bf[1][0], bf[1][2]);
                mma16816(acc[mi][3], af[mi], bf[1][1], bf[1][3]);
            }
        }
        __syncthreads();   // barrier 2: MMA reads done before buffers overwritten
    }
}

// ---------------------------------------------------------------------------
// Projection GEMM (gate & up in one launch): z=0 -> w1 -> g_gate,
//                                            z=1 -> w3 -> g_up. fp16 out.
// grid (T/128, I/64, 2)
// ---------------------------------------------------------------------------
__global__ void __launch_bounds__(256, 2) gemm_proj(
    const int* __restrict__ w1q, const float* __restrict__ w1s, const float* __restrict__ w1z,
    const int* __restrict__ w3q, const float* __restrict__ w3s, const float* __restrict__ w3z)
{
    extern __shared__ char smem[];
    const int t0 = blockIdx.x * 128;
    const int i0 = blockIdx.y * 64;
    const bool up = blockIdx.z != 0;

    const int*   wq = up ? w3q : w1q;
    const float* ws = up ? w3s : w1s;
    const float* wz = up ? w3z : w1z;
    __half* outp = up ? g_up : g_gate;

    const int tid = threadIdx.x;
    const int br  = tid >> 2;

    GemmCore g;
    g.gA = g_xh; g.lda = H_DIM;
    g.wq_row = wq + (size_t)(i0 + br) * H_DIM + (tid & 3) * 16;
    g.ws_row = ws + (size_t)(i0 + br) * NG1;
    g.wz_row = wz + (size_t)(i0 + br) * NG1;
    g.t0 = t0; g.nchunks = NG1; g.kc0 = 0;

    float acc[2][4][4];
#pragma unroll
    for (int mi = 0; mi < 2; mi++)
#pragma unroll
        for (int ni = 0; ni < 4; ni++)
#pragma unroll
            for (int r = 0; r < 4; r++) acc[mi][ni][r] = 0.f;

    gemm_core_run(g, smem, acc);

    const int lane = tid & 31, wid = tid >> 5, wm = wid & 3, wn = wid >> 2;
#pragma unroll
    for (int mi = 0; mi < 2; mi++) {
#pragma unroll
        for (int ni = 0; ni < 4; ni++) {
            int r0  = t0 + wm * 32 + mi * 16 + (lane >> 2);
            int col = i0 + wn * 32 + ni * 8 + (lane & 3) * 2;
            *(__half2*)&outp[(size_t)r0 * I_DIM + col] =
                __floats2half2_rn(acc[mi][ni][0], acc[mi][ni][1]);
            *(__half2*)&outp[(size_t)(r0 + 8) * I_DIM + col] =
                __floats2half2_rn(acc[mi][ni][2], acc[mi][ni][3]);
        }
    }
}

// ---------------------------------------------------------------------------
// Activation: g_hh = silu(g_gate) * g_up  (fp16 in/out; 8 elems/thread)
// ---------------------------------------------------------------------------
__global__ void act_kernel() {
    int i = (blockIdx.x * blockDim.x + threadIdx.x) * 8;
    uint4 gv = *(const uint4*)&g_gate[i];
    uint4 uv = *(const uint4*)&g_up[i];
    const uint32_t* gp = (const uint32_t*)&gv;
    const uint32_t* upp = (const uint32_t*)&uv;
    uint4 hv;
    uint32_t* hp = (uint32_t*)&hv;
#pragma unroll
    for (int j = 0; j < 4; j++) {
        __half2 gh = *(const __half2*)&gp[j];
        __half2 uh = *(const __half2*)&upp[j];
        float g0 = __low2float(gh), g1 = __high2float(gh);
        float u0 = __low2float(uh), u1 = __high2float(uh);
        float h0 = g0 / (1.f + __expf(-g0)) * u0;
        float h1 = g1 / (1.f + __expf(-g1)) * u1;
        hp[j] = h2_as_u32(__floats2half2_rn(h0, h1));
    }
    *(uint4*)&g_hh[i] = hv;
}

// ---------------------------------------------------------------------------
// Down GEMM, split-K=4: partials into g_part[z]. grid (T/128, H/64, 4)
// ---------------------------------------------------------------------------
__global__ void __launch_bounds__(256, 2) gemm_down(
    const int* __restrict__ wq, const float* __restrict__ ws, const float* __restrict__ wz)
{
    extern __shared__ char smem[];
    const int t0  = blockIdx.x * 128;
    const int h0  = blockIdx.y * 64;
    const int spl = blockIdx.z;

    const int tid = threadIdx.x;
    const int br  = tid >> 2;

    GemmCore g;
    g.gA = g_hh; g.lda = I_DIM;
    g.wq_row = wq + (size_t)(h0 + br) * I_DIM + (tid & 3) * 16;
    g.ws_row = ws + (size_t)(h0 + br) * NG2;
    g.wz_row = wz + (size_t)(h0 + br) * NG2;
    g.t0 = t0; g.nchunks = NC2_SPLIT; g.kc0 = spl * NC2_SPLIT;

    float acc[2][4][4];
#pragma unroll
    for (int mi = 0; mi < 2; mi++)
#pragma unroll
        for (int ni = 0; ni < 4; ni++)
#pragma unroll
            for (int r = 0; r < 4; r++) acc[mi][ni][r] = 0.f;

    gemm_core_run(g, smem, acc);

    const int lane = tid & 31, wid = tid >> 5, wm = wid & 3, wn = wid >> 2;
    float* outp = g_part[spl];
#pragma unroll
    for (int mi = 0; mi < 2; mi++) {
#pragma unroll
        for (int ni = 0; ni < 4; ni++) {
            int r0  = t0 + wm * 32 + mi * 16 + (lane >> 2);
            int col = h0 + wn * 32 + ni * 8 + (lane & 3) * 2;
            *(float2*)&outp[(size_t)r0 * H_DIM + col] =
                make_float2(acc[mi][ni][0], acc[mi][ni][1]);
            *(float2*)&outp[(size_t)(r0 + 8) * H_DIM + col] =
                make_float2(acc[mi][ni][2], acc[mi][ni][3]);
        }
    }
}

// ---------------------------------------------------------------------------
// Reduce split-K partials -> out
// ---------------------------------------------------------------------------
__global__ void reduce_kernel(float* __restrict__ out) {
    int i = (blockIdx.x * blockDim.x + threadIdx.x) * 4;
    float4 a = *(const float4*)&g_part[0][i];
    float4 b = *(const float4*)&g_part[1][i];
    float4 c = *(const float4*)&g_part[2][i];
    float4 d = *(const float4*)&g_part[3][i];
    float4 r;
    r.x = (a.x + b.x) + (c.x + d.x);
    r.y = (a.y + b.y) + (c.y + d.y);
    r.z = (a.z + b.z) + (c.z + d.z);
    r.w = (a.w + b.w) + (c.w + d.w);
    *(float4*)&out[i] = r;
}

// ---------------------------------------------------------------------------
#define SMEM_GEMM (2 * 128 * SSTR * 2 + 2 * 64 * SSTR * 2)   // 55.3 KB

extern "C" void kernel_launch(void* const* d_in, const int* in_sizes, int n_in,
                              void* d_out, int out_size) {
    (void)in_sizes; (void)n_in; (void)out_size;
    const float* x   = (const float*)d_in[0];
    const int*   w1q = (const int*)  d_in[1];
    const float* w1s = (const float*)d_in[2];
    const float* w1z = (const float*)d_in[3];
    const int*   w3q = (const int*)  d_in[4];
    const float* w3s = (const float*)d_in[5];
    const float* w3z = (const float*)d_in[6];
    const int*   w2q = (const int*)  d_in[7];
    const float* w2s = (const float*)d_in[8];
    const float* w2z = (const float*)d_in[9];
    float* out = (float*)d_out;

    cudaFuncSetAttribute(gemm_proj, cudaFuncAttributeMaxDynamicSharedMemorySize, SMEM_GEMM);
    cudaFuncSetAttribute(gemm_down, cudaFuncAttributeMaxDynamicSharedMemorySize, SMEM_GEMM);

    cvt_x_kernel<<<(T_DIM * H_DIM) / 1024, 256>>>(x);
    gemm_proj<<<dim3(T_DIM / 128, I_DIM / 64, 2), 256, SMEM_GEMM>>>(w1q, w1s, w1z, w3q, w3s, w3z);
    act_kernel<<<(T_DIM * I_DIM) / 2048, 256>>>();
    gemm_down<<<dim3(T_DIM / 128, H_DIM / 64, KSPLIT), 256, SMEM_GEMM>>>(w2q, w2s, w2z);
    reduce_kernel<<<(T_DIM * H_DIM) / 1024, 256>>>(out);
}

// round 15
// speedup vs baseline: 1.1956x; 1.0031x over previous
#include <cuda_runtime.h>
#include <cuda_fp16.h>
#include <cstdint>

// Problem dims (fixed)
#define T_DIM 256
#define H_DIM 4096
#define I_DIM 14336
#define GS 64
#define NG1 (H_DIM / GS)   // 64
#define NG2 (I_DIM / GS)   // 224
#define KSPLIT 4
#define NC2_SPLIT (NG2 / KSPLIT)   // 56 chunks per split

#define SSTR 72            // smem row stride in halves (64 + 8 pad)

// Scratch (static __device__: allocation-free per harness rules)
__device__ __half g_xh[T_DIM * H_DIM];              // x in fp16
__device__ __half g_gate[T_DIM * I_DIM];            // raw gate fp16
__device__ __half g_up[T_DIM * I_DIM];              // raw up fp16
__device__ __half g_hh[T_DIM * I_DIM];              // silu(gate)*up fp16
__device__ float  g_part[KSPLIT][T_DIM * H_DIM];    // down-GEMM split-K partials

__device__ __forceinline__ uint32_t h2_as_u32(__half2 h) {
    union { __half2 h2; uint32_t u; } cvt; cvt.h2 = h; return cvt.u;
}
__device__ __forceinline__ unsigned smem_u32(const void* p) {
    return (unsigned)__cvta_generic_to_shared(p);
}
__device__ __forceinline__ void cp_async16(void* dst, const void* src) {
    asm volatile("cp.async.cg.shared.global [%0], [%1], 16;\n"
                 :: "r"(smem_u32(dst)), "l"(src));
}
__device__ __forceinline__ void cp_commit() { asm volatile("cp.async.commit_group;\n"); }
template<int N> __device__ __forceinline__ void cp_wait() {
    asm volatile("cp.async.wait_group %0;\n" :: "n"(N));
    __syncwarp();
}
__device__ __forceinline__ void mma16816(float* c, const uint32_t* a, uint32_t b0, uint32_t b1) {
    asm volatile(
        "mma.sync.aligned.m16n8k16.row.col.f32.f16.f16.f32 "
        "{%0,%1,%2,%3}, {%4,%5,%6,%7}, {%8,%9}, {%0,%1,%2,%3};\n"
        : "+f"(c[0]), "+f"(c[1]), "+f"(c[2]), "+f"(c[3])
        : "r"(a[0]), "r"(a[1]), "r"(a[2]), "r"(a[3]), "r"(b0), "r"(b1));
}
__device__ __forceinline__ void ldsm4(uint32_t* r, uint32_t addr) {
    asm volatile("ldmatrix.sync.aligned.m8n8.x4.shared.b16 {%0,%1,%2,%3}, [%4];"
                 : "=r"(r[0]), "=r"(r[1]), "=r"(r[2]), "=r"(r[3]) : "r"(addr));
}

// ---------------------------------------------------------------------------
// Kernel 0: x fp32 -> fp16
// ---------------------------------------------------------------------------
__global__ void cvt_x_kernel(const float* __restrict__ x) {
    int i = (blockIdx.x * blockDim.x + threadIdx.x) * 4;
    float4 v = *(const float4*)(x + i);
    *(__half2*)&g_xh[i]     = __floats2half2_rn(v.x, v.y);
    *(__half2*)&g_xh[i + 2] = __floats2half2_rn(v.z, v.w);
}

// ---------------------------------------------------------------------------
// Shared GEMM core (R7 structure + fragment double-buffering):
// BM=128, BN=64, BK=64, 256 threads (8 warps, 4x2), warp tile 32x32.
// A cp.async double-buffered; B int32 HQQ register-staged one chunk ahead,
// dequant -> fp16 smem. LDSM for k-step ks+1 issued before MMAs of ks.
// Two barriers per chunk; 2 CTAs/SM.
// ---------------------------------------------------------------------------
struct GemmCore {
    const __half* gA; int lda;
    const int* wq_row; const float* ws_row; const float* wz_row;
    int t0;
    int nchunks; int kc0;   // chunk range [kc0, kc0+nchunks)
};

__device__ __forceinline__ void gemm_core_run(const GemmCore& g, char* smem, float acc[2][4][4]) {
    __half* As = (__half*)smem;                          // [2][128][SSTR]
    __half* Bs = (__half*)(smem + 2 * 128 * SSTR * 2);   // [2][64][SSTR]

    const int tid  = threadIdx.x;
    const int lane = tid & 31;
    const int wid  = tid >> 5;
    const int wm   = wid & 3;
    const int wn   = wid >> 2;

    const int br = tid >> 2;          // 0..63
    const int bk = (tid & 3) * 16;

    int4 q[4]; float s, z;

    // prologue: A chunk 0, B chunk 0
#pragma unroll
    for (int j = 0; j < 4; j++) {
        int v = tid + j * 256, r = v >> 3, c = (v & 7) * 8;
        cp_async16(As + r * SSTR + c, g.gA + (size_t)(g.t0 + r) * g.lda + g.kc0 * 64 + c);
    }
    cp_commit();
#pragma unroll
    for (int j = 0; j < 4; j++) q[j] = *(const int4*)(g.wq_row + (size_t)g.kc0 * 64 + j * 4);
    s = g.ws_row[g.kc0]; z = g.wz_row[g.kc0];

    // ldmatrix per-lane addresses (bytes)
    const int lrow = lane & 15, lcol = lane >> 4;
    const uint32_t As_u = smem_u32(As);
    const uint32_t Bs_u = smem_u32(Bs);
    uint32_t a_addr[2], b_addr[2];
#pragma unroll
    for (int mi = 0; mi < 2; mi++)
        a_addr[mi] = As_u + ((wm * 32 + mi * 16 + lrow) * SSTR + lcol * 8) * 2;
#pragma unroll
    for (int nj = 0; nj < 2; nj++)
        b_addr[nj] = Bs_u + ((wn * 32 + nj * 16 + lrow) * SSTR + lcol * 8) * 2;

    const int NC = g.nchunks;
    for (int kl = 0; kl < NC; kl++) {
        const int buf = kl & 1;
        if (kl + 1 < NC) {
#pragma unroll
            for (int j = 0; j < 4; j++) {
                int v = tid + j * 256, r = v >> 3, c = (v & 7) * 8;
                cp_async16(As + (buf ^ 1) * 128 * SSTR + r * SSTR + c,
                           g.gA + (size_t)(g.t0 + r) * g.lda + (g.kc0 + kl + 1) * 64 + c);
            }
            cp_commit();
            cp_wait<1>();      // own-thread A[kl] landed
        } else {
            cp_wait<0>();
        }

        // dequant staged B[kl] -> fp16 smem
        {
            __half* bp = Bs + buf * 64 * SSTR + br * SSTR + bk;
#pragma unroll
            for (int jj = 0; jj < 2; jj++) {
                uint4 v;
                int4 qa = q[jj * 2], qb = q[jj * 2 + 1];
                v.x = h2_as_u32(__floats2half2_rn(((float)qa.x - z) * s, ((float)qa.y - z) * s));
                v.y = h2_as_u32(__floats2half2_rn(((float)qa.z - z) * s, ((float)qa.w - z) * s));
                v.z = h2_as_u32(__floats2half2_rn(((float)qb.x - z) * s, ((float)qb.y - z) * s));
                v.w = h2_as_u32(__floats2half2_rn(((float)qb.z - z) * s, ((float)qb.w - z) * s));
                *(uint4*)(bp + jj * 8) = v;
            }
        }
        __syncthreads();   // barrier 1: STS done AND all threads' A-waits passed

        if (kl + 1 < NC) {   // stage B[kl+1] (LDG hidden under MMA)
#pragma unroll
            for (int j = 0; j < 4; j++)
                q[j] = *(const int4*)(g.wq_row + (size_t)(g.kc0 + kl + 1) * 64 + j * 4);
            s = g.ws_row[g.kc0 + kl + 1]; z = g.wz_row[g.kc0 + kl + 1];
        }

        const uint32_t abuf = buf * 128 * SSTR * 2;
        const uint32_t bbuf = buf * 64 * SSTR * 2;

        // fragment double-buffered MMA loop: LDSM for ks+1 before MMAs of ks
        uint32_t af[2][2][4], bf[2][2][4];
        ldsm4(af[0][0], a_addr[0] + abuf);
        ldsm4(af[0][1], a_addr[1] + abuf);
        ldsm4(bf[0][0], b_addr[0] + bbuf);
        ldsm4(bf[0][1], b_addr[1] + bbuf);
#pragma unroll
        for (int ks = 0; ks < 4; ks++) {
            const int cur = ks & 1, nxt = cur ^ 1;
            if (ks < 3) {
                const uint32_t ko = (ks + 1) * 32;
                ldsm4(af[nxt][0], a_addr[0] + abuf + ko);
                ldsm4(af[nxt][1], a_addr[1] + abuf + ko);
                ldsm4(bf[nxt][0], b_addr[0] + bbuf + ko);
                ldsm4(bf[nxt][1], b_addr[1] + bbuf + ko);
            }
#pragma unroll
            for (int mi = 0; mi < 2; mi++) {
                mma16816(acc[mi][0], af[cur][mi], bf[cur][0][0], bf[cur][0][2]);
                mma16816(acc[mi][1], af[cur][mi], bf[cur][0][1], bf[cur][0][3]);
                mma16816(acc[mi][2], af[cur][mi], bf[cur][1][0], bf[cur][1][2]);
                mma16816(acc[mi][3], af[cur][mi], bf[cur][1][1], bf[cur][1][3]);
            }
        }
        __syncthreads();   // barrier 2: MMA reads done before buffers overwritten
    }
}

// ---------------------------------------------------------------------------
// Projection GEMM (gate & up in one launch): z=0 -> w1 -> g_gate,
//                                            z=1 -> w3 -> g_up. fp16 out.
// grid (T/128, I/64, 2)
// ---------------------------------------------------------------------------
__global__ void __launch_bounds__(256, 2) gemm_proj(
    const int* __restrict__ w1q, const float* __restrict__ w1s, const float* __restrict__ w1z,
    const int* __restrict__ w3q, const float* __restrict__ w3s, const float* __restrict__ w3z)
{
    extern __shared__ char smem[];
    const int t0 = blockIdx.x * 128;
    const int i0 = blockIdx.y * 64;
    const bool up = blockIdx.z != 0;

    const int*   wq = up ? w3q : w1q;
    const float* ws = up ? w3s : w1s;
    const float* wz = up ? w3z : w1z;
    __half* outp = up ? g_up : g_gate;

    const int tid = threadIdx.x;
    const int br  = tid >> 2;

    GemmCore g;
    g.gA = g_xh; g.lda = H_DIM;
    g.wq_row = wq + (size_t)(i0 + br) * H_DIM + (tid & 3) * 16;
    g.ws_row = ws + (size_t)(i0 + br) * NG1;
    g.wz_row = wz + (size_t)(i0 + br) * NG1;
    g.t0 = t0; g.nchunks = NG1; g.kc0 = 0;

    float acc[2][4][4];
#pragma unroll
    for (int mi = 0; mi < 2; mi++)
#pragma unroll
        for (int ni = 0; ni < 4; ni++)
#pragma unroll
            for (int r = 0; r < 4; r++) acc[mi][ni][r] = 0.f;

    gemm_core_run(g, smem, acc);

    const int lane = tid & 31, wid = tid >> 5, wm = wid & 3, wn = wid >> 2;
#pragma unroll
    for (int mi = 0; mi < 2; mi++) {
#pragma unroll
        for (int ni = 0; ni < 4; ni++) {
            int r0  = t0 + wm * 32 + mi * 16 + (lane >> 2);
            int col = i0 + wn * 32 + ni * 8 + (lane & 3) * 2;
            *(__half2*)&outp[(size_t)r0 * I_DIM + col] =
                __floats2half2_rn(acc[mi][ni][0], acc[mi][ni][1]);
            *(__half2*)&outp[(size_t)(r0 + 8) * I_DIM + col] =
                __floats2half2_rn(acc[mi][ni][2], acc[mi][ni][3]);
        }
    }
}

// ---------------------------------------------------------------------------
// Activation: g_hh = silu(g_gate) * g_up  (fp16 in/out; 8 elems/thread)
// ---------------------------------------------------------------------------
__global__ void act_kernel() {
    int i = (blockIdx.x * blockDim.x + threadIdx.x) * 8;
    uint4 gv = *(const uint4*)&g_gate[i];
    uint4 uv = *(const uint4*)&g_up[i];
    const uint32_t* gp = (const uint32_t*)&gv;
    const uint32_t* upp = (const uint32_t*)&uv;
    uint4 hv;
    uint32_t* hp = (uint32_t*)&hv;
#pragma unroll
    for (int j = 0; j < 4; j++) {
        __half2 gh = *(const __half2*)&gp[j];
        __half2 uh = *(const __half2*)&upp[j];
        float g0 = __low2float(gh), g1 = __high2float(gh);
        float u0 = __low2float(uh), u1 = __high2float(uh);
        float h0 = g0 / (1.f + __expf(-g0)) * u0;
        float h1 = g1 / (1.f + __expf(-g1)) * u1;
        hp[j] = h2_as_u32(__floats2half2_rn(h0, h1));
    }
    *(uint4*)&g_hh[i] = hv;
}

// ---------------------------------------------------------------------------
// Down GEMM, split-K=4: partials into g_part[z]. grid (T/128, H/64, 4)
// ---------------------------------------------------------------------------
__global__ void __launch_bounds__(256, 2) gemm_down(
    const int* __restrict__ wq, const float* __restrict__ ws, const float* __restrict__ wz)
{
    extern __shared__ char smem[];
    const int t0  = blockIdx.x * 128;
    const int h0  = blockIdx.y * 64;
    const int spl = blockIdx.z;

    const int tid = threadIdx.x;
    const int br  = tid >> 2;

    GemmCore g;
    g.gA = g_hh; g.lda = I_DIM;
    g.wq_row = wq + (size_t)(h0 + br) * I_DIM + (tid & 3) * 16;
    g.ws_row = ws + (size_t)(h0 + br) * NG2;
    g.wz_row = wz + (size_t)(h0 + br) * NG2;
    g.t0 = t0; g.nchunks = NC2_SPLIT; g.kc0 = spl * NC2_SPLIT;

    float acc[2][4][4];
#pragma unroll
    for (int mi = 0; mi < 2; mi++)
#pragma unroll
        for (int ni = 0; ni < 4; ni++)
#pragma unroll
            for (int r = 0; r < 4; r++) acc[mi][ni][r] = 0.f;

    gemm_core_run(g, smem, acc);

    const int lane = tid & 31, wid = tid >> 5, wm = wid & 3, wn = wid >> 2;
    float* outp = g_part[spl];
#pragma unroll
    for (int mi = 0; mi < 2; mi++) {
#pragma unroll
        for (int ni = 0; ni < 4; ni++) {
            int r0  = t0 + wm * 32 + mi * 16 + (lane >> 2);
            int col = h0 + wn * 32 + ni * 8 + (lane & 3) * 2;
            *(float2*)&outp[(size_t)r0 * H_DIM + col] =
                make_float2(acc[mi][ni][0], acc[mi][ni][1]);
            *(float2*)&outp[(size_t)(r0 + 8) * H_DIM + col] =
                make_float2(acc[mi][ni][2], acc[mi][ni][3]);
        }
    }
}

// ---------------------------------------------------------------------------
// Reduce split-K partials -> out
// ---------------------------------------------------------------------------
__global__ void reduce_kernel(float* __restrict__ out) {
    int i = (blockIdx.x * blockDim.x + threadIdx.x) * 4;
    float4 a = *(const float4*)&g_part[0][i];
    float4 b = *(const float4*)&g_part[1][i];
    float4 c = *(const float4*)&g_part[2][i];
    float4 d = *(const float4*)&g_part[3][i];
    float4 r;
    r.x = (a.x + b.x) + (c.x + d.x);
    r.y = (a.y + b.y) + (c.y + d.y);
    r.z = (a.z + b.z) + (c.z + d.z);
    r.w = (a.w + b.w) + (c.w + d.w);
    *(float4*)&out[i] = r;
}

// ---------------------------------------------------------------------------
#define SMEM_GEMM (2 * 128 * SSTR * 2 + 2 * 64 * SSTR * 2)   // 55.3 KB

extern "C" void kernel_launch(void* const* d_in, const int* in_sizes, int n_in,
                              void* d_out, int out_size) {
    (void)in_sizes; (void)n_in; (void)out_size;
    const float* x   = (const float*)d_in[0];
    const int*   w1q = (const int*)  d_in[1];
    const float* w1s = (const float*)d_in[2];
    const float* w1z = (const float*)d_in[3];
    const int*   w3q = (const int*)  d_in[4];
    const float* w3s = (const float*)d_in[5];
    const float* w3z = (const float*)d_in[6];
    const int*   w2q = (const int*)  d_in[7];
    const float* w2s = (const float*)d_in[8];
    const float* w2z = (const float*)d_in[9];
    float* out = (float*)d_out;

    cudaFuncSetAttribute(gemm_proj, cudaFuncAttributeMaxDynamicSharedMemorySize, SMEM_GEMM);
    cudaFuncSetAttribute(gemm_down, cudaFuncAttributeMaxDynamicSharedMemorySize, SMEM_GEMM);

    cvt_x_kernel<<<(T_DIM * H_DIM) / 1024, 256>>>(x);
    gemm_proj<<<dim3(T_DIM / 128, I_DIM / 64, 2), 256, SMEM_GEMM>>>(w1q, w1s, w1z, w3q, w3s, w3z);
    act_kernel<<<(T_DIM * I_DIM) / 2048, 256>>>();
    gemm_down<<<dim3(T_DIM / 128, H_DIM / 64, KSPLIT), 256, SMEM_GEMM>>>(w2q, w2s, w2z);
    reduce_kernel<<<(T_DIM * H_DIM) / 1024, 256>>>(out);
}